// round 2
// baseline (speedup 1.0000x reference)
#include <cuda_runtime.h>
#include <cstdint>

#define N_NODES 100000
#define N_EDGES 1600000
#define NFEAT   512
#define NHID    256
#define NCLASS  40
#define NF4     (NCLASS / 4)   // 10 float4 per feature row

#define SCAN_T  1024
#define NBLK    ((N_NODES + SCAN_T - 1) / SCAN_T)   // 98

// ---------------- scratch (static device globals; no allocation) ----------------
__device__ float g_h1[(size_t)N_NODES * NHID];     // 102.4 MB
__device__ float g_h2[(size_t)N_NODES * NHID];     // 102.4 MB
__device__ float g_h [(size_t)N_NODES * NCLASS];   // 16 MB
__device__ float g_vA[(size_t)N_NODES * NCLASS];   // 16 MB
__device__ float g_vB[(size_t)N_NODES * NCLASS];   // 16 MB
__device__ float g_dinv[N_NODES];
__device__ int   g_cnt [N_NODES];
__device__ int   g_fill[N_NODES];
__device__ int   g_rowstart[N_NODES + 1];
__device__ int   g_cols[N_EDGES];
__device__ int   g_bsum[128];

// ---------------- packed f32x2 helpers ----------------
__device__ __forceinline__ void ffma2(unsigned long long& d,
                                      unsigned long long a,
                                      unsigned long long b) {
    asm("fma.rn.f32x2 %0, %1, %2, %0;" : "+l"(d) : "l"(a), "l"(b));
}
__device__ __forceinline__ unsigned long long pack_dup(float x) {
    unsigned long long r;
    unsigned int xi = __float_as_uint(x);
    asm("mov.b64 %0, {%1, %1};" : "=l"(r) : "r"(xi));
    return r;
}
__device__ __forceinline__ void unpack2(unsigned long long v, float& lo, float& hi) {
    unsigned int a, b;
    asm("mov.b64 {%0, %1}, %2;" : "=r"(a), "=r"(b) : "l"(v));
    lo = __uint_as_float(a); hi = __uint_as_float(b);
}

// ---------------- graph preprocessing ----------------
__global__ void zero_counts() {
    int i = blockIdx.x * blockDim.x + threadIdx.x;
    if (i < N_NODES) { g_cnt[i] = 0; g_fill[i] = 0; }
}

__global__ void count_deg(const int* __restrict__ rows) {
    int e = blockIdx.x * blockDim.x + threadIdx.x;
    if (e < N_EDGES) atomicAdd(&g_cnt[rows[e]], 1);
}

__global__ void compute_dinv() {
    int i = blockIdx.x * blockDim.x + threadIdx.x;
    if (i < N_NODES) g_dinv[i] = 1.0f / (float)(g_cnt[i] + 1);  // +1 self loop
}

__global__ void scan_blocks() {
    __shared__ int s[SCAN_T];
    int t   = threadIdx.x;
    int gid = blockIdx.x * SCAN_T + t;
    int v   = (gid < N_NODES) ? g_cnt[gid] : 0;
    s[t] = v;
    __syncthreads();
    #pragma unroll
    for (int off = 1; off < SCAN_T; off <<= 1) {
        int x = (t >= off) ? s[t - off] : 0;
        __syncthreads();
        s[t] += x;
        __syncthreads();
    }
    if (gid < N_NODES) g_rowstart[gid] = s[t] - v;    // exclusive
    if (t == SCAN_T - 1) g_bsum[blockIdx.x] = s[t];
}

__global__ void scan_offsets() {
    if (threadIdx.x == 0 && blockIdx.x == 0) {
        int acc = 0;
        for (int i = 0; i < NBLK; i++) { int t = g_bsum[i]; g_bsum[i] = acc; acc += t; }
        g_rowstart[N_NODES] = acc;
    }
}

__global__ void scan_add() {
    int t   = threadIdx.x;
    int gid = blockIdx.x * SCAN_T + t;
    if (gid < N_NODES) g_rowstart[gid] += g_bsum[blockIdx.x];
}

__global__ void scatter_edges(const int* __restrict__ rows, const int* __restrict__ cols) {
    int e = blockIdx.x * blockDim.x + threadIdx.x;
    if (e < N_EDGES) {
        int r   = rows[e];
        int pos = g_rowstart[r] + atomicAdd(&g_fill[r], 1);
        g_cols[pos] = cols[e];
    }
}

// ---------------- GEMM (NT): C[n,m] = A[n,:].B[m,:], packed f32x2 math ----------------
#define BM 128
#define BK 16
#define TM 8
#define ASTRIDE (BM + 4)   // 132 floats: 16B-aligned rows, reduced STS conflicts

template<int BN, int TN, int RELU>
__global__ __launch_bounds__(256)
void gemm_f32x2(const float* __restrict__ A, const float* __restrict__ B,
                const float* __restrict__ bias, float* __restrict__ C,
                int Nrows, int M, int K)
{
    constexpr int NT2    = TN / 2;
    constexpr int BSTRIDE = BN + 4;
    constexpr int ALOADS = (BM * BK) / (4 * 256);  // 2
    constexpr int BLOADS = (BN * BK) / (4 * 256);  // 2 (BN=128) or 1 (BN=64)

    __shared__ float As[2][BK][ASTRIDE];
    __shared__ float Bs[2][BK][BSTRIDE];

    const int tx  = threadIdx.x;          // 0..15
    const int ty  = threadIdx.y;          // 0..15
    const int tid = ty * 16 + tx;
    const int rowBase = blockIdx.y * BM;
    const int colBase = blockIdx.x * BN;
    const int nsteps  = K / BK;

    unsigned long long acc[TM][NT2];
    #pragma unroll
    for (int i = 0; i < TM; i++)
        #pragma unroll
        for (int j = 0; j < NT2; j++) acc[i][j] = 0ULL;

    float4 pa[ALOADS];
    float4 pb[BLOADS];

    // ---- prefetch tile 0 into registers ----
    {
        #pragma unroll
        for (int l = 0; l < ALOADS; l++) {
            int idx = tid + l * 256;
            int ar  = idx >> 2;
            int kq  = (idx & 3) << 2;
            int gr  = rowBase + ar;
            pa[l] = make_float4(0.f, 0.f, 0.f, 0.f);
            if (gr < Nrows) pa[l] = *(const float4*)(A + (size_t)gr * K + kq);
        }
        #pragma unroll
        for (int l = 0; l < BLOADS; l++) {
            int idx = tid + l * 256;
            int br  = idx >> (BLOADS == 2 ? 2 : 2);
            int kq  = (idx & 3) << 2;
            if (BLOADS == 1) { br = tid >> 2; kq = (tid & 3) << 2; }
            int gm = colBase + br;
            pb[l] = make_float4(0.f, 0.f, 0.f, 0.f);
            if (gm < M) pb[l] = *(const float4*)(B + (size_t)gm * K + kq);
        }
    }
    // store tile 0
    {
        #pragma unroll
        for (int l = 0; l < ALOADS; l++) {
            int idx = tid + l * 256;
            int ar  = idx >> 2;
            int kq  = (idx & 3) << 2;
            As[0][kq + 0][ar] = pa[l].x; As[0][kq + 1][ar] = pa[l].y;
            As[0][kq + 2][ar] = pa[l].z; As[0][kq + 3][ar] = pa[l].w;
        }
        #pragma unroll
        for (int l = 0; l < BLOADS; l++) {
            int idx = tid + l * 256;
            int br  = idx >> 2;
            int kq  = (idx & 3) << 2;
            if (BLOADS == 1) { br = tid >> 2; kq = (tid & 3) << 2; }
            Bs[0][kq + 0][br] = pb[l].x; Bs[0][kq + 1][br] = pb[l].y;
            Bs[0][kq + 2][br] = pb[l].z; Bs[0][kq + 3][br] = pb[l].w;
        }
    }
    __syncthreads();

    for (int step = 0; step < nsteps; step++) {
        const int cur = step & 1;
        const int nxt = cur ^ 1;
        const int k0n = (step + 1) * BK;

        // issue prefetch of next tile (global -> regs)
        if (step + 1 < nsteps) {
            #pragma unroll
            for (int l = 0; l < ALOADS; l++) {
                int idx = tid + l * 256;
                int ar  = idx >> 2;
                int kq  = (idx & 3) << 2;
                int gr  = rowBase + ar;
                pa[l] = make_float4(0.f, 0.f, 0.f, 0.f);
                if (gr < Nrows) pa[l] = *(const float4*)(A + (size_t)gr * K + k0n + kq);
            }
            #pragma unroll
            for (int l = 0; l < BLOADS; l++) {
                int idx = tid + l * 256;
                int br  = idx >> 2;
                int kq  = (idx & 3) << 2;
                if (BLOADS == 1) { br = tid >> 2; kq = (tid & 3) << 2; }
                int gm = colBase + br;
                pb[l] = make_float4(0.f, 0.f, 0.f, 0.f);
                if (gm < M) pb[l] = *(const float4*)(B + (size_t)gm * K + k0n + kq);
            }
        }

        // compute on current tile
        #pragma unroll
        for (int k = 0; k < BK; k++) {
            float4 a0 = *(const float4*)&As[cur][k][ty * TM];
            float4 a1 = *(const float4*)&As[cur][k][ty * TM + 4];
            unsigned long long bp[NT2];
            {
                ulonglong2 b0 = *(const ulonglong2*)&Bs[cur][k][tx * TN];
                bp[0] = b0.x; bp[1] = b0.y;
                if (NT2 == 4) {
                    ulonglong2 b1 = *(const ulonglong2*)&Bs[cur][k][tx * TN + 4];
                    bp[2] = b1.x; bp[3] = b1.y;
                }
            }
            float av[TM] = {a0.x, a0.y, a0.z, a0.w, a1.x, a1.y, a1.z, a1.w};
            #pragma unroll
            for (int i = 0; i < TM; i++) {
                unsigned long long ap = pack_dup(av[i]);
                #pragma unroll
                for (int j = 0; j < NT2; j++) ffma2(acc[i][j], ap, bp[j]);
            }
        }

        // store next tile (regs -> smem)
        if (step + 1 < nsteps) {
            #pragma unroll
            for (int l = 0; l < ALOADS; l++) {
                int idx = tid + l * 256;
                int ar  = idx >> 2;
                int kq  = (idx & 3) << 2;
                As[nxt][kq + 0][ar] = pa[l].x; As[nxt][kq + 1][ar] = pa[l].y;
                As[nxt][kq + 2][ar] = pa[l].z; As[nxt][kq + 3][ar] = pa[l].w;
            }
            #pragma unroll
            for (int l = 0; l < BLOADS; l++) {
                int idx = tid + l * 256;
                int br  = idx >> 2;
                int kq  = (idx & 3) << 2;
                if (BLOADS == 1) { br = tid >> 2; kq = (tid & 3) << 2; }
                Bs[nxt][kq + 0][br] = pb[l].x; Bs[nxt][kq + 1][br] = pb[l].y;
                Bs[nxt][kq + 2][br] = pb[l].z; Bs[nxt][kq + 3][br] = pb[l].w;
            }
            __syncthreads();
        }
    }

    // ---- epilogue: bias + optional relu, float4 stores ----
    #pragma unroll
    for (int i = 0; i < TM; i++) {
        int gr = rowBase + ty * TM + i;
        if (gr >= Nrows) continue;
        float c[TN];
        #pragma unroll
        for (int j = 0; j < NT2; j++) unpack2(acc[i][j], c[2 * j], c[2 * j + 1]);
        #pragma unroll
        for (int q = 0; q < TN / 4; q++) {
            int gm = colBase + tx * TN + q * 4;
            if (gm < M) {
                float4 bb = *(const float4*)(bias + gm);
                float4 o;
                o.x = c[q * 4 + 0] + bb.x; o.y = c[q * 4 + 1] + bb.y;
                o.z = c[q * 4 + 2] + bb.z; o.w = c[q * 4 + 3] + bb.w;
                if (RELU) {
                    o.x = fmaxf(o.x, 0.f); o.y = fmaxf(o.y, 0.f);
                    o.z = fmaxf(o.z, 0.f); o.w = fmaxf(o.w, 0.f);
                }
                *(float4*)(C + (size_t)gr * M + gm) = o;
            }
        }
    }
}

// ---------------- SpMM power-iteration step ----------------
// out[r] = 0.5*dinv[r]*(sum_{edges r->c} v[c] + v[r]) + 0.5*h[r]
__global__ __launch_bounds__(320)
void spmm_step(const float4* __restrict__ v4, const float4* __restrict__ h4,
               float4* __restrict__ out4)
{
    int t = blockIdx.x * 320 + threadIdx.x;
    int r = t / NF4;
    int f = t - r * NF4;
    if (r >= N_NODES) return;

    int s = g_rowstart[r];
    int e = g_rowstart[r + 1];

    float ax = 0.f, ay = 0.f, az = 0.f, aw = 0.f;
    int i = s;
    for (; i + 4 <= e; i += 4) {
        int c0 = g_cols[i + 0], c1 = g_cols[i + 1];
        int c2 = g_cols[i + 2], c3 = g_cols[i + 3];
        float4 p0 = __ldg(v4 + (size_t)c0 * NF4 + f);
        float4 p1 = __ldg(v4 + (size_t)c1 * NF4 + f);
        float4 p2 = __ldg(v4 + (size_t)c2 * NF4 + f);
        float4 p3 = __ldg(v4 + (size_t)c3 * NF4 + f);
        ax += (p0.x + p1.x) + (p2.x + p3.x);
        ay += (p0.y + p1.y) + (p2.y + p3.y);
        az += (p0.z + p1.z) + (p2.z + p3.z);
        aw += (p0.w + p1.w) + (p2.w + p3.w);
    }
    for (; i < e; i++) {
        int c = g_cols[i];
        float4 p = __ldg(v4 + (size_t)c * NF4 + f);
        ax += p.x; ay += p.y; az += p.z; aw += p.w;
    }

    float4 vr = __ldg(v4 + (size_t)r * NF4 + f);
    float4 hr = __ldg(h4 + (size_t)r * NF4 + f);
    float  w  = 0.5f * g_dinv[r];

    float4 o;
    o.x = w * (ax + vr.x) + 0.5f * hr.x;
    o.y = w * (ay + vr.y) + 0.5f * hr.y;
    o.z = w * (az + vr.z) + 0.5f * hr.z;
    o.w = w * (aw + vr.w) + 0.5f * hr.w;
    out4[(size_t)r * NF4 + f] = o;
}

// ---------------- host ----------------
extern "C" void kernel_launch(void* const* d_in, const int* in_sizes, int n_in,
                              void* d_out, int out_size)
{
    const float* x  = (const float*)d_in[0];
    const int*   ei = (const int*)  d_in[1];
    const float* W1 = (const float*)d_in[2];
    const float* b1 = (const float*)d_in[3];
    const float* W2 = (const float*)d_in[4];
    const float* b2 = (const float*)d_in[5];
    const float* W3 = (const float*)d_in[6];
    const float* b3 = (const float*)d_in[7];
    float* out = (float*)d_out;

    const int* rows = ei;            // edge_index[0]
    const int* cols = ei + N_EDGES;  // edge_index[1]

    void *p;
    float *h1, *h2, *h, *vA, *vB;
    cudaGetSymbolAddress(&p, g_h1); h1 = (float*)p;
    cudaGetSymbolAddress(&p, g_h2); h2 = (float*)p;
    cudaGetSymbolAddress(&p, g_h);  h  = (float*)p;
    cudaGetSymbolAddress(&p, g_vA); vA = (float*)p;
    cudaGetSymbolAddress(&p, g_vB); vB = (float*)p;

    // ---- CSR build ----
    zero_counts <<<(N_NODES + 255) / 256, 256>>>();
    count_deg   <<<(N_EDGES + 255) / 256, 256>>>(rows);
    compute_dinv<<<(N_NODES + 255) / 256, 256>>>();
    scan_blocks <<<NBLK, SCAN_T>>>();
    scan_offsets<<<1, 32>>>();
    scan_add    <<<NBLK, SCAN_T>>>();
    scatter_edges<<<(N_EDGES + 255) / 256, 256>>>(rows, cols);

    // ---- MLP (f32x2 GEMMs) ----
    dim3 blk(16, 16);
    dim3 g1((NHID   + 127) / 128, (N_NODES + BM - 1) / BM);
    dim3 g3((NCLASS + 63)  / 64,  (N_NODES + BM - 1) / BM);
    gemm_f32x2<128, 8, 1><<<g1, blk>>>(x,  W1, b1, h1, N_NODES, NHID,   NFEAT);
    gemm_f32x2<128, 8, 1><<<g1, blk>>>(h1, W2, b2, h2, N_NODES, NHID,   NHID);
    gemm_f32x2< 64, 4, 0><<<g3, blk>>>(h2, W3, b3, h,  N_NODES, NCLASS, NHID);

    // ---- 10 power iterations, ping-pong, last writes d_out ----
    const int SP_G = (N_NODES * NF4 + 319) / 320;
    const float* src = h;
    for (int it = 0; it < 10; it++) {
        float* dst = (it == 9) ? out : ((it & 1) ? vB : vA);
        spmm_step<<<SP_G, 320>>>((const float4*)src, (const float4*)h, (float4*)dst);
        src = dst;
    }
}

// round 5
// speedup vs baseline: 1.9138x; 1.9138x over previous
#include <cuda_runtime.h>
#include <cuda_bf16.h>
#include <cstdint>

#define N_NODES 100000
#define N_EDGES 1600000
#define NFEAT   512
#define NHID    256
#define NCLASS  40
#define NF4     (NCLASS / 4)

#define SCAN_T  1024
#define NBLK    ((N_NODES + SCAN_T - 1) / SCAN_T)   // 98

// ---------------- scratch (static device globals; no allocation) ----------------
__device__ float g_h1[(size_t)N_NODES * NHID];
__device__ float g_h2[(size_t)N_NODES * NHID];
__device__ float g_h [(size_t)N_NODES * NCLASS];
__device__ float g_vA[(size_t)N_NODES * NCLASS];
__device__ float g_vB[(size_t)N_NODES * NCLASS];
__device__ float g_dinv[N_NODES];
__device__ int   g_cnt [N_NODES];
__device__ int   g_fill[N_NODES];
__device__ int   g_rowstart[N_NODES + 1];
__device__ int   g_cols[N_EDGES];
__device__ int   g_bsum[128];

// ---------------- helpers ----------------
__device__ __forceinline__ uint32_t smem_u32(const void* p) {
    uint32_t a;
    asm("{ .reg .u64 t; cvta.to.shared.u64 t, %1; cvt.u32.u64 %0, t; }" : "=r"(a) : "l"(p));
    return a;
}

__device__ __forceinline__ void mma16816(float c[4], const uint32_t a[4],
                                         uint32_t b0, uint32_t b1) {
    asm volatile(
        "mma.sync.aligned.m16n8k16.row.col.f32.bf16.bf16.f32 "
        "{%0,%1,%2,%3}, {%4,%5,%6,%7}, {%8,%9}, {%0,%1,%2,%3};"
        : "+f"(c[0]), "+f"(c[1]), "+f"(c[2]), "+f"(c[3])
        : "r"(a[0]), "r"(a[1]), "r"(a[2]), "r"(a[3]), "r"(b0), "r"(b1));
}

#define LDSM_X4(r0, r1, r2, r3, addr) \
    asm volatile("ldmatrix.sync.aligned.m8n8.x4.shared.b16 {%0,%1,%2,%3}, [%4];" \
                 : "=r"(r0), "=r"(r1), "=r"(r2), "=r"(r3) : "r"(addr))

// split fp32x4 -> packed bf16 hi (uint2) and lo (uint2)
__device__ __forceinline__ void split4(float4 v, uint2& hi, uint2& lo) {
    __nv_bfloat16 hx = __float2bfloat16(v.x);
    __nv_bfloat16 hy = __float2bfloat16(v.y);
    __nv_bfloat16 hz = __float2bfloat16(v.z);
    __nv_bfloat16 hw = __float2bfloat16(v.w);
    __nv_bfloat16 lx = __float2bfloat16(v.x - __bfloat162float(hx));
    __nv_bfloat16 ly = __float2bfloat16(v.y - __bfloat162float(hy));
    __nv_bfloat16 lz = __float2bfloat16(v.z - __bfloat162float(hz));
    __nv_bfloat16 lw = __float2bfloat16(v.w - __bfloat162float(hw));
    hi.x = ((uint32_t)__bfloat16_as_ushort(hy) << 16) | __bfloat16_as_ushort(hx);
    hi.y = ((uint32_t)__bfloat16_as_ushort(hw) << 16) | __bfloat16_as_ushort(hz);
    lo.x = ((uint32_t)__bfloat16_as_ushort(ly) << 16) | __bfloat16_as_ushort(lx);
    lo.y = ((uint32_t)__bfloat16_as_ushort(lw) << 16) | __bfloat16_as_ushort(lz);
}

// ---------------- graph preprocessing ----------------
__global__ void zero_counts() {
    int i = blockIdx.x * blockDim.x + threadIdx.x;
    if (i < N_NODES) { g_cnt[i] = 0; g_fill[i] = 0; }
}
__global__ void count_deg(const int* __restrict__ rows) {
    int e = blockIdx.x * blockDim.x + threadIdx.x;
    if (e < N_EDGES) atomicAdd(&g_cnt[rows[e]], 1);
}
__global__ void compute_dinv() {
    int i = blockIdx.x * blockDim.x + threadIdx.x;
    if (i < N_NODES) g_dinv[i] = 1.0f / (float)(g_cnt[i] + 1);
}
__global__ void scan_blocks() {
    __shared__ int s[SCAN_T];
    int t   = threadIdx.x;
    int gid = blockIdx.x * SCAN_T + t;
    int v   = (gid < N_NODES) ? g_cnt[gid] : 0;
    s[t] = v;
    __syncthreads();
    #pragma unroll
    for (int off = 1; off < SCAN_T; off <<= 1) {
        int x = (t >= off) ? s[t - off] : 0;
        __syncthreads();
        s[t] += x;
        __syncthreads();
    }
    if (gid < N_NODES) g_rowstart[gid] = s[t] - v;
    if (t == SCAN_T - 1) g_bsum[blockIdx.x] = s[t];
}
__global__ void scan_offsets() {
    if (threadIdx.x == 0 && blockIdx.x == 0) {
        int acc = 0;
        for (int i = 0; i < NBLK; i++) { int t = g_bsum[i]; g_bsum[i] = acc; acc += t; }
        g_rowstart[N_NODES] = acc;
    }
}
__global__ void scan_add() {
    int t   = threadIdx.x;
    int gid = blockIdx.x * SCAN_T + t;
    if (gid < N_NODES) g_rowstart[gid] += g_bsum[blockIdx.x];
}
__global__ void scatter_edges(const int* __restrict__ rows, const int* __restrict__ cols) {
    int e = blockIdx.x * blockDim.x + threadIdx.x;
    if (e < N_EDGES) {
        int r   = rows[e];
        int pos = g_rowstart[r] + atomicAdd(&g_fill[r], 1);
        g_cols[pos] = cols[e];
    }
}

// =============== HMMA GEMM: C[n, 0:M] = A[n, 0:K] @ W[0:M, 0:K]^T + bias ===============
// 3-term bf16 split (Ahi*Bhi + Ahi*Blo + Alo*Bhi), fp32 accumulate.
// CTA tile: 128 x BN, K-tile 32. 8 warps: 4 along M (32 rows), 2 along N (BN/2 cols).
#define RS 40              // smem row stride in bf16 (80 bytes) - conflict-free ldmatrix
#define RSB 80             // bytes

template<int BN, int RELU>
__global__ __launch_bounds__(256, 2)
void gemm_hmma(const float* __restrict__ A, const float* __restrict__ W,
               const float* __restrict__ bias, float* __restrict__ C,
               int Nrows, int Mcols, int K)
{
    constexpr int NJ      = BN / 16;            // 8-col groups per warp
    constexpr int ABYTES  = 128 * RSB;          // 10240
    constexpr int BBYTES  = BN * RSB;
    constexpr int OFF_AHI = 0;
    constexpr int OFF_ALO = ABYTES;
    constexpr int OFF_BHI = 2 * ABYTES;
    constexpr int OFF_BLO = 2 * ABYTES + BBYTES;
    constexpr int OFF_BS  = 2 * ABYTES + 2 * BBYTES;
    constexpr int BLOADS  = BN / 32;            // float4 B loads per thread

    __shared__ __align__(16) char sm[OFF_BS + BN * 4];

    const uint32_t smb = smem_u32(sm);
    const int tid = threadIdx.x;
    const int wid = tid >> 5;
    const int lid = tid & 31;
    const int warpM = (wid & 3) * 32;
    const int warpN = (wid >> 2) * (BN / 2);
    const int rowBase = blockIdx.y * 128;
    const int colBase = blockIdx.x * BN;

    // bias -> smem
    for (int i = tid; i < BN; i += 256) {
        int gc = colBase + i;
        *(float*)(sm + OFF_BS + i * 4) = (gc < Mcols) ? bias[gc] : 0.0f;
    }

    // per-lane ldmatrix address components
    const int aRow  = (lid & 7) + ((lid >> 3) & 1) * 8;     // 0..15
    const int aColB = (lid >> 4) * 16;                      // 0 or 16 bytes
    const int bN    = ((lid >> 4) * 8) + (lid & 7);         // 0..15
    const int bColB = ((lid >> 3) & 1) * 16;

    const uint32_t aAddr0 = smb + OFF_AHI + (warpM + aRow) * RSB + aColB;
    const uint32_t bAddr0 = smb + OFF_BHI + (warpN + bN) * RSB + bColB;

    float acc[2][NJ][4];
    #pragma unroll
    for (int i = 0; i < 2; i++)
        #pragma unroll
        for (int j = 0; j < NJ; j++)
            #pragma unroll
            for (int q = 0; q < 4; q++) acc[i][j][q] = 0.0f;

    for (int kt = 0; kt < K; kt += 32) {
        __syncthreads();
        // ---- load + split A tile: 128 x 32 fp32 ----
        #pragma unroll
        for (int i = 0; i < 4; i++) {
            int idx = tid + i * 256;
            int row = idx >> 3;
            int c4  = idx & 7;
            int gr  = rowBase + row;
            float4 v = make_float4(0.f, 0.f, 0.f, 0.f);
            if (gr < Nrows) v = *(const float4*)(A + (size_t)gr * K + kt + c4 * 4);
            uint2 hi, lo; split4(v, hi, lo);
            *(uint2*)(sm + OFF_AHI + row * RSB + c4 * 8) = hi;
            *(uint2*)(sm + OFF_ALO + row * RSB + c4 * 8) = lo;
        }
        // ---- load + split B tile: BN x 32 fp32 ----
        #pragma unroll
        for (int i = 0; i < BLOADS; i++) {
            int idx = tid + i * 256;
            int row = idx >> 3;
            int c4  = idx & 7;
            int gm  = colBase + row;
            float4 v = make_float4(0.f, 0.f, 0.f, 0.f);
            if (gm < Mcols) v = *(const float4*)(W + (size_t)gm * K + kt + c4 * 4);
            uint2 hi, lo; split4(v, hi, lo);
            *(uint2*)(sm + OFF_BHI + row * RSB + c4 * 8) = hi;
            *(uint2*)(sm + OFF_BLO + row * RSB + c4 * 8) = lo;
        }
        __syncthreads();

        #pragma unroll
        for (int ks = 0; ks < 2; ks++) {
            const uint32_t kOff = ks * 32;
            uint32_t ah[2][4], al[2][4];
            #pragma unroll
            for (int i = 0; i < 2; i++) {
                uint32_t aa = aAddr0 + i * 16 * RSB + kOff;
                LDSM_X4(ah[i][0], ah[i][1], ah[i][2], ah[i][3], aa);
                LDSM_X4(al[i][0], al[i][1], al[i][2], al[i][3], aa + ABYTES);
            }
            #pragma unroll
            for (int jp = 0; jp < NJ / 2; jp++) {
                uint32_t bb = bAddr0 + jp * 16 * RSB + kOff;
                uint32_t bh0, bh1, bh2, bh3, bl0, bl1, bl2, bl3;
                LDSM_X4(bh0, bh1, bh2, bh3, bb);
                LDSM_X4(bl0, bl1, bl2, bl3, bb + BBYTES);
                #pragma unroll
                for (int i = 0; i < 2; i++) {
                    mma16816(acc[i][2 * jp],     ah[i], bh0, bh1);
                    mma16816(acc[i][2 * jp],     ah[i], bl0, bl1);
                    mma16816(acc[i][2 * jp],     al[i], bh0, bh1);
                    mma16816(acc[i][2 * jp + 1], ah[i], bh2, bh3);
                    mma16816(acc[i][2 * jp + 1], ah[i], bl2, bl3);
                    mma16816(acc[i][2 * jp + 1], al[i], bh2, bh3);
                }
            }
        }
    }

    // ---- epilogue ----
    const int rBase = rowBase + warpM + (lid >> 2);
    const int cOff  = warpN + (lid & 3) * 2;
    #pragma unroll
    for (int i = 0; i < 2; i++) {
        #pragma unroll
        for (int j = 0; j < NJ; j++) {
            int cl = cOff + j * 8;
            int gc = colBase + cl;
            if (gc >= Mcols) continue;
            float2 bb = *(const float2*)(sm + OFF_BS + cl * 4);
            int r0 = rBase + i * 16;
            int r1 = r0 + 8;
            float2 v0, v1;
            v0.x = acc[i][j][0] + bb.x; v0.y = acc[i][j][1] + bb.y;
            v1.x = acc[i][j][2] + bb.x; v1.y = acc[i][j][3] + bb.y;
            if (RELU) {
                v0.x = fmaxf(v0.x, 0.f); v0.y = fmaxf(v0.y, 0.f);
                v1.x = fmaxf(v1.x, 0.f); v1.y = fmaxf(v1.y, 0.f);
            }
            if (r0 < Nrows) *(float2*)(C + (size_t)r0 * Mcols + gc) = v0;
            if (r1 < Nrows) *(float2*)(C + (size_t)r1 * Mcols + gc) = v1;
        }
    }
}

// ---------------- SpMM power-iteration step ----------------
__global__ __launch_bounds__(320)
void spmm_step(const float4* __restrict__ v4, const float4* __restrict__ h4,
               float4* __restrict__ out4)
{
    int t = blockIdx.x * 320 + threadIdx.x;
    int r = t / NF4;
    int f = t - r * NF4;
    if (r >= N_NODES) return;

    int s = g_rowstart[r];
    int e = g_rowstart[r + 1];

    float ax = 0.f, ay = 0.f, az = 0.f, aw = 0.f;
    int i = s;
    for (; i + 4 <= e; i += 4) {
        int c0 = g_cols[i + 0], c1 = g_cols[i + 1];
        int c2 = g_cols[i + 2], c3 = g_cols[i + 3];
        float4 p0 = __ldg(v4 + (size_t)c0 * NF4 + f);
        float4 p1 = __ldg(v4 + (size_t)c1 * NF4 + f);
        float4 p2 = __ldg(v4 + (size_t)c2 * NF4 + f);
        float4 p3 = __ldg(v4 + (size_t)c3 * NF4 + f);
        ax += (p0.x + p1.x) + (p2.x + p3.x);
        ay += (p0.y + p1.y) + (p2.y + p3.y);
        az += (p0.z + p1.z) + (p2.z + p3.z);
        aw += (p0.w + p1.w) + (p2.w + p3.w);
    }
    for (; i < e; i++) {
        int c = g_cols[i];
        float4 p = __ldg(v4 + (size_t)c * NF4 + f);
        ax += p.x; ay += p.y; az += p.z; aw += p.w;
    }

    float4 vr = __ldg(v4 + (size_t)r * NF4 + f);
    float4 hr = __ldg(h4 + (size_t)r * NF4 + f);
    float  w  = 0.5f * g_dinv[r];

    float4 o;
    o.x = w * (ax + vr.x) + 0.5f * hr.x;
    o.y = w * (ay + vr.y) + 0.5f * hr.y;
    o.z = w * (az + vr.z) + 0.5f * hr.z;
    o.w = w * (aw + vr.w) + 0.5f * hr.w;
    out4[(size_t)r * NF4 + f] = o;
}

// ---------------- host ----------------
extern "C" void kernel_launch(void* const* d_in, const int* in_sizes, int n_in,
                              void* d_out, int out_size)
{
    const float* x  = (const float*)d_in[0];
    const int*   ei = (const int*)  d_in[1];
    const float* W1 = (const float*)d_in[2];
    const float* b1 = (const float*)d_in[3];
    const float* W2 = (const float*)d_in[4];
    const float* b2 = (const float*)d_in[5];
    const float* W3 = (const float*)d_in[6];
    const float* b3 = (const float*)d_in[7];
    float* out = (float*)d_out;

    const int* rows = ei;
    const int* cols = ei + N_EDGES;

    void *p;
    float *h1, *h2, *h, *vA, *vB;
    cudaGetSymbolAddress(&p, g_h1); h1 = (float*)p;
    cudaGetSymbolAddress(&p, g_h2); h2 = (float*)p;
    cudaGetSymbolAddress(&p, g_h);  h  = (float*)p;
    cudaGetSymbolAddress(&p, g_vA); vA = (float*)p;
    cudaGetSymbolAddress(&p, g_vB); vB = (float*)p;

    // ---- CSR build ----
    zero_counts <<<(N_NODES + 255) / 256, 256>>>();
    count_deg   <<<(N_EDGES + 255) / 256, 256>>>(rows);
    compute_dinv<<<(N_NODES + 255) / 256, 256>>>();
    scan_blocks <<<NBLK, SCAN_T>>>();
    scan_offsets<<<1, 32>>>();
    scan_add    <<<NBLK, SCAN_T>>>();
    scatter_edges<<<(N_EDGES + 255) / 256, 256>>>(rows, cols);

    // ---- MLP via HMMA bf16 3-term split ----
    const int MG = (N_NODES + 127) / 128;   // 782
    gemm_hmma<128, 1><<<dim3(2, MG), 256>>>(x,  W1, b1, h1, N_NODES, NHID,   NFEAT);
    gemm_hmma<128, 1><<<dim3(2, MG), 256>>>(h1, W2, b2, h2, N_NODES, NHID,   NHID);
    gemm_hmma< 64, 0><<<dim3(1, MG), 256>>>(h2, W3, b3, h,  N_NODES, NCLASS, NHID);

    // ---- 10 power iterations ----
    const int SP_G = (N_NODES * NF4 + 319) / 320;
    const float* src = h;
    for (int it = 0; it < 10; it++) {
        float* dst = (it == 9) ? out : ((it & 1) ? vB : vA);
        spmm_step<<<SP_G, 320>>>((const float4*)src, (const float4*)h, (float4*)dst);
        src = dst;
    }
}

// round 6
// speedup vs baseline: 2.0290x; 1.0602x over previous
#include <cuda_runtime.h>
#include <cuda_bf16.h>
#include <cstdint>

#define N_NODES 100000
#define N_EDGES 1600000
#define NFEAT   512
#define NHID    256
#define NCLASS  40
#define NF4     (NCLASS / 4)

#define SCAN_T  1024
#define NBLK    ((N_NODES + SCAN_T - 1) / SCAN_T)   // 98

// ---------------- scratch (static device globals; no allocation) ----------------
// g_h1/g_h2 hold bf16 hi|lo pairs (aliased): hi at [0, N*256), lo at [N*256, 2N*256) bf16
__device__ float g_h1[(size_t)N_NODES * NHID];
__device__ float g_h2[(size_t)N_NODES * NHID];
__device__ float g_h [(size_t)N_NODES * NCLASS];
__device__ float g_vA[(size_t)N_NODES * NCLASS];
__device__ float g_vB[(size_t)N_NODES * NCLASS];
__device__ float g_dinv[N_NODES];
__device__ int   g_cnt [N_NODES];
__device__ int   g_fill[N_NODES];
__device__ int   g_rowstart[N_NODES + 1];
__device__ int   g_cols[N_EDGES];
__device__ int   g_bsum[128];

// ---------------- helpers ----------------
__device__ __forceinline__ uint32_t smem_u32(const void* p) {
    uint32_t a;
    asm("{ .reg .u64 t; cvta.to.shared.u64 t, %1; cvt.u32.u64 %0, t; }" : "=r"(a) : "l"(p));
    return a;
}

__device__ __forceinline__ void mma16816(float c[4], const uint32_t a[4],
                                         uint32_t b0, uint32_t b1) {
    asm volatile(
        "mma.sync.aligned.m16n8k16.row.col.f32.bf16.bf16.f32 "
        "{%0,%1,%2,%3}, {%4,%5,%6,%7}, {%8,%9}, {%0,%1,%2,%3};"
        : "+f"(c[0]), "+f"(c[1]), "+f"(c[2]), "+f"(c[3])
        : "r"(a[0]), "r"(a[1]), "r"(a[2]), "r"(a[3]), "r"(b0), "r"(b1));
}

#define LDSM_X4(r0, r1, r2, r3, addr) \
    asm volatile("ldmatrix.sync.aligned.m8n8.x4.shared.b16 {%0,%1,%2,%3}, [%4];" \
                 : "=r"(r0), "=r"(r1), "=r"(r2), "=r"(r3) : "r"(addr))

// split fp32x4 -> packed bf16 hi (uint2) and lo (uint2)
__device__ __forceinline__ void split4(float4 v, uint2& hi, uint2& lo) {
    __nv_bfloat16 hx = __float2bfloat16(v.x);
    __nv_bfloat16 hy = __float2bfloat16(v.y);
    __nv_bfloat16 hz = __float2bfloat16(v.z);
    __nv_bfloat16 hw = __float2bfloat16(v.w);
    __nv_bfloat16 lx = __float2bfloat16(v.x - __bfloat162float(hx));
    __nv_bfloat16 ly = __float2bfloat16(v.y - __bfloat162float(hy));
    __nv_bfloat16 lz = __float2bfloat16(v.z - __bfloat162float(hz));
    __nv_bfloat16 lw = __float2bfloat16(v.w - __bfloat162float(hw));
    hi.x = ((uint32_t)__bfloat16_as_ushort(hy) << 16) | __bfloat16_as_ushort(hx);
    hi.y = ((uint32_t)__bfloat16_as_ushort(hw) << 16) | __bfloat16_as_ushort(hz);
    lo.x = ((uint32_t)__bfloat16_as_ushort(ly) << 16) | __bfloat16_as_ushort(lx);
    lo.y = ((uint32_t)__bfloat16_as_ushort(lw) << 16) | __bfloat16_as_ushort(lz);
}

// split a float2 into bf16x2 hi + lo packed words
__device__ __forceinline__ void split2(float2 v, uint32_t& hi, uint32_t& lo) {
    __nv_bfloat16 hx = __float2bfloat16(v.x);
    __nv_bfloat16 hy = __float2bfloat16(v.y);
    __nv_bfloat16 lx = __float2bfloat16(v.x - __bfloat162float(hx));
    __nv_bfloat16 ly = __float2bfloat16(v.y - __bfloat162float(hy));
    hi = ((uint32_t)__bfloat16_as_ushort(hy) << 16) | __bfloat16_as_ushort(hx);
    lo = ((uint32_t)__bfloat16_as_ushort(ly) << 16) | __bfloat16_as_ushort(lx);
}

// ---------------- graph preprocessing ----------------
__global__ void zero_counts() {
    int i = blockIdx.x * blockDim.x + threadIdx.x;
    if (i < N_NODES) { g_cnt[i] = 0; g_fill[i] = 0; }
}
__global__ void count_deg(const int* __restrict__ rows) {
    int e = blockIdx.x * blockDim.x + threadIdx.x;
    if (e < N_EDGES) atomicAdd(&g_cnt[rows[e]], 1);
}
__global__ void compute_dinv() {
    int i = blockIdx.x * blockDim.x + threadIdx.x;
    if (i < N_NODES) g_dinv[i] = 1.0f / (float)(g_cnt[i] + 1);
}
__global__ void scan_blocks() {
    __shared__ int s[SCAN_T];
    int t   = threadIdx.x;
    int gid = blockIdx.x * SCAN_T + t;
    int v   = (gid < N_NODES) ? g_cnt[gid] : 0;
    s[t] = v;
    __syncthreads();
    #pragma unroll
    for (int off = 1; off < SCAN_T; off <<= 1) {
        int x = (t >= off) ? s[t - off] : 0;
        __syncthreads();
        s[t] += x;
        __syncthreads();
    }
    if (gid < N_NODES) g_rowstart[gid] = s[t] - v;
    if (t == SCAN_T - 1) g_bsum[blockIdx.x] = s[t];
}
__global__ void scan_offsets() {
    if (threadIdx.x == 0 && blockIdx.x == 0) {
        int acc = 0;
        for (int i = 0; i < NBLK; i++) { int t = g_bsum[i]; g_bsum[i] = acc; acc += t; }
        g_rowstart[N_NODES] = acc;
    }
}
__global__ void scan_add() {
    int t   = threadIdx.x;
    int gid = blockIdx.x * SCAN_T + t;
    if (gid < N_NODES) g_rowstart[gid] += g_bsum[blockIdx.x];
}
__global__ void scatter_edges(const int* __restrict__ rows, const int* __restrict__ cols) {
    int e = blockIdx.x * blockDim.x + threadIdx.x;
    if (e < N_EDGES) {
        int r   = rows[e];
        int pos = g_rowstart[r] + atomicAdd(&g_fill[r], 1);
        g_cols[pos] = cols[e];
    }
}

// =============== HMMA GEMM with bf16 3-term split, K-tile 64 ===============
// ABF16=0: A is fp32 (split in-kernel).  ABF16=1: A given as bf16 hi/lo arrays.
// OUTSPLIT=1: write bf16 hi/lo outputs (for next layer).  OUTSPLIT=0: write fp32 C.
#define RSB 144            // smem row stride bytes for 64 bf16 cols (128B data + 16B pad)

template<int BN, int RELU, int ABF16, int OUTSPLIT>
__global__ __launch_bounds__(256, 2)
void gemm_hmma(const float* __restrict__ Af,
               const __nv_bfloat16* __restrict__ Ahi_g,
               const __nv_bfloat16* __restrict__ Alo_g,
               const float* __restrict__ W,
               const float* __restrict__ bias,
               float* __restrict__ C,
               __nv_bfloat16* __restrict__ Chi,
               __nv_bfloat16* __restrict__ Clo,
               int Nrows, int Mcols, int K)
{
    constexpr int NJ      = BN / 16;
    constexpr int ABYTES  = 128 * RSB;          // 18432
    constexpr int BBYTES  = BN * RSB;
    constexpr int OFF_AHI = 0;
    constexpr int OFF_ALO = ABYTES;
    constexpr int OFF_BHI = 2 * ABYTES;
    constexpr int OFF_BLO = 2 * ABYTES + BBYTES;
    constexpr int OFF_BS  = 2 * ABYTES + 2 * BBYTES;
    constexpr int BLOADS  = BN / 16;            // f32 float4 B loads per thread (K-tile 64)

    extern __shared__ __align__(16) char sm[];

    const uint32_t smb = smem_u32(sm);
    const int tid = threadIdx.x;
    const int wid = tid >> 5;
    const int lid = tid & 31;
    const int warpM = (wid & 3) * 32;
    const int warpN = (wid >> 2) * (BN / 2);
    const int rowBase = blockIdx.y * 128;
    const int colBase = blockIdx.x * BN;

    // bias -> smem
    for (int i = tid; i < BN; i += 256) {
        int gc = colBase + i;
        *(float*)(sm + OFF_BS + i * 4) = (gc < Mcols) ? bias[gc] : 0.0f;
    }

    // per-lane ldmatrix address components
    const int aRow  = (lid & 7) + ((lid >> 3) & 1) * 8;
    const int aColB = (lid >> 4) * 16;
    const int bN    = ((lid >> 4) * 8) + (lid & 7);
    const int bColB = ((lid >> 3) & 1) * 16;

    const uint32_t aAddr0 = smb + OFF_AHI + (warpM + aRow) * RSB + aColB;
    const uint32_t bAddr0 = smb + OFF_BHI + (warpN + bN) * RSB + bColB;

    float acc[2][NJ][4];
    #pragma unroll
    for (int i = 0; i < 2; i++)
        #pragma unroll
        for (int j = 0; j < NJ; j++)
            #pragma unroll
            for (int q = 0; q < 4; q++) acc[i][j][q] = 0.0f;

    for (int kt = 0; kt < K; kt += 64) {
        __syncthreads();
        // ---- A tile: 128 rows x 64 cols ----
        if (ABF16) {
            // direct bf16 hi/lo loads, 4x uint4 per array per thread
            #pragma unroll
            for (int i = 0; i < 4; i++) {
                int idx = tid + i * 256;       // 0..1023
                int row = idx >> 3;
                int c8  = idx & 7;
                int gr  = rowBase + row;
                uint4 vh = make_uint4(0, 0, 0, 0);
                uint4 vl = make_uint4(0, 0, 0, 0);
                if (gr < Nrows) {
                    vh = *(const uint4*)(Ahi_g + (size_t)gr * K + kt + c8 * 8);
                    vl = *(const uint4*)(Alo_g + (size_t)gr * K + kt + c8 * 8);
                }
                *(uint4*)(sm + OFF_AHI + row * RSB + c8 * 16) = vh;
                *(uint4*)(sm + OFF_ALO + row * RSB + c8 * 16) = vl;
            }
        } else {
            // fp32 load + split, 8x float4 per thread
            #pragma unroll
            for (int i = 0; i < 8; i++) {
                int idx = tid + i * 256;       // 0..2047
                int row = idx >> 4;
                int c4  = idx & 15;
                int gr  = rowBase + row;
                float4 v = make_float4(0.f, 0.f, 0.f, 0.f);
                if (gr < Nrows) v = *(const float4*)(Af + (size_t)gr * K + kt + c4 * 4);
                uint2 hi, lo; split4(v, hi, lo);
                *(uint2*)(sm + OFF_AHI + row * RSB + c4 * 8) = hi;
                *(uint2*)(sm + OFF_ALO + row * RSB + c4 * 8) = lo;
            }
        }
        // ---- B tile: BN rows x 64 cols fp32 (split) ----
        #pragma unroll
        for (int i = 0; i < BLOADS; i++) {
            int idx = tid + i * 256;
            int row = idx >> 4;
            int c4  = idx & 15;
            int gm  = colBase + row;
            float4 v = make_float4(0.f, 0.f, 0.f, 0.f);
            if (gm < Mcols) v = *(const float4*)(W + (size_t)gm * K + kt + c4 * 4);
            uint2 hi, lo; split4(v, hi, lo);
            *(uint2*)(sm + OFF_BHI + row * RSB + c4 * 8) = hi;
            *(uint2*)(sm + OFF_BLO + row * RSB + c4 * 8) = lo;
        }
        __syncthreads();

        #pragma unroll
        for (int ks = 0; ks < 4; ks++) {
            const uint32_t kOff = ks * 32;     // 16 bf16 = 32 bytes per k-step
            uint32_t ah[2][4], al[2][4];
            #pragma unroll
            for (int i = 0; i < 2; i++) {
                uint32_t aa = aAddr0 + i * 16 * RSB + kOff;
                LDSM_X4(ah[i][0], ah[i][1], ah[i][2], ah[i][3], aa);
                LDSM_X4(al[i][0], al[i][1], al[i][2], al[i][3], aa + ABYTES);
            }
            #pragma unroll
            for (int jp = 0; jp < NJ / 2; jp++) {
                uint32_t bb = bAddr0 + jp * 16 * RSB + kOff;
                uint32_t bh0, bh1, bh2, bh3, bl0, bl1, bl2, bl3;
                LDSM_X4(bh0, bh1, bh2, bh3, bb);
                LDSM_X4(bl0, bl1, bl2, bl3, bb + BBYTES);
                #pragma unroll
                for (int i = 0; i < 2; i++) {
                    mma16816(acc[i][2 * jp],     ah[i], bh0, bh1);
                    mma16816(acc[i][2 * jp],     ah[i], bl0, bl1);
                    mma16816(acc[i][2 * jp],     al[i], bh0, bh1);
                    mma16816(acc[i][2 * jp + 1], ah[i], bh2, bh3);
                    mma16816(acc[i][2 * jp + 1], ah[i], bl2, bl3);
                    mma16816(acc[i][2 * jp + 1], al[i], bh2, bh3);
                }
            }
        }
    }

    // ---- epilogue ----
    const int rBase = rowBase + warpM + (lid >> 2);
    const int cOff  = warpN + (lid & 3) * 2;
    #pragma unroll
    for (int i = 0; i < 2; i++) {
        #pragma unroll
        for (int j = 0; j < NJ; j++) {
            int cl = cOff + j * 8;
            int gc = colBase + cl;
            if (gc >= Mcols) continue;
            float2 bb = *(const float2*)(sm + OFF_BS + cl * 4);
            int r0 = rBase + i * 16;
            int r1 = r0 + 8;
            float2 v0, v1;
            v0.x = acc[i][j][0] + bb.x; v0.y = acc[i][j][1] + bb.y;
            v1.x = acc[i][j][2] + bb.x; v1.y = acc[i][j][3] + bb.y;
            if (RELU) {
                v0.x = fmaxf(v0.x, 0.f); v0.y = fmaxf(v0.y, 0.f);
                v1.x = fmaxf(v1.x, 0.f); v1.y = fmaxf(v1.y, 0.f);
            }
            if (OUTSPLIT) {
                uint32_t h0, l0, h1v, l1;
                split2(v0, h0, l0);
                split2(v1, h1v, l1);
                if (r0 < Nrows) {
                    *(uint32_t*)(Chi + (size_t)r0 * Mcols + gc) = h0;
                    *(uint32_t*)(Clo + (size_t)r0 * Mcols + gc) = l0;
                }
                if (r1 < Nrows) {
                    *(uint32_t*)(Chi + (size_t)r1 * Mcols + gc) = h1v;
                    *(uint32_t*)(Clo + (size_t)r1 * Mcols + gc) = l1;
                }
            } else {
                if (r0 < Nrows) *(float2*)(C + (size_t)r0 * Mcols + gc) = v0;
                if (r1 < Nrows) *(float2*)(C + (size_t)r1 * Mcols + gc) = v1;
            }
        }
    }
}

// ---------------- SpMM power-iteration step ----------------
__global__ __launch_bounds__(320)
void spmm_step(const float4* __restrict__ v4, const float4* __restrict__ h4,
               float4* __restrict__ out4)
{
    int t = blockIdx.x * 320 + threadIdx.x;
    int r = t / NF4;
    int f = t - r * NF4;
    if (r >= N_NODES) return;

    int s = g_rowstart[r];
    int e = g_rowstart[r + 1];

    float ax = 0.f, ay = 0.f, az = 0.f, aw = 0.f;
    int i = s;
    for (; i + 4 <= e; i += 4) {
        int c0 = g_cols[i + 0], c1 = g_cols[i + 1];
        int c2 = g_cols[i + 2], c3 = g_cols[i + 3];
        float4 p0 = __ldg(v4 + (size_t)c0 * NF4 + f);
        float4 p1 = __ldg(v4 + (size_t)c1 * NF4 + f);
        float4 p2 = __ldg(v4 + (size_t)c2 * NF4 + f);
        float4 p3 = __ldg(v4 + (size_t)c3 * NF4 + f);
        ax += (p0.x + p1.x) + (p2.x + p3.x);
        ay += (p0.y + p1.y) + (p2.y + p3.y);
        az += (p0.z + p1.z) + (p2.z + p3.z);
        aw += (p0.w + p1.w) + (p2.w + p3.w);
    }
    for (; i < e; i++) {
        int c = g_cols[i];
        float4 p = __ldg(v4 + (size_t)c * NF4 + f);
        ax += p.x; ay += p.y; az += p.z; aw += p.w;
    }

    float4 vr = __ldg(v4 + (size_t)r * NF4 + f);
    float4 hr = __ldg(h4 + (size_t)r * NF4 + f);
    float  w  = 0.5f * g_dinv[r];

    float4 o;
    o.x = w * (ax + vr.x) + 0.5f * hr.x;
    o.y = w * (ay + vr.y) + 0.5f * hr.y;
    o.z = w * (az + vr.z) + 0.5f * hr.z;
    o.w = w * (aw + vr.w) + 0.5f * hr.w;
    out4[(size_t)r * NF4 + f] = o;
}

// ---------------- host ----------------
extern "C" void kernel_launch(void* const* d_in, const int* in_sizes, int n_in,
                              void* d_out, int out_size)
{
    const float* x  = (const float*)d_in[0];
    const int*   ei = (const int*)  d_in[1];
    const float* W1 = (const float*)d_in[2];
    const float* b1 = (const float*)d_in[3];
    const float* W2 = (const float*)d_in[4];
    const float* b2 = (const float*)d_in[5];
    const float* W3 = (const float*)d_in[6];
    const float* b3 = (const float*)d_in[7];
    float* out = (float*)d_out;

    const int* rows = ei;
    const int* cols = ei + N_EDGES;

    void *p;
    float *h1, *h2, *h, *vA, *vB;
    cudaGetSymbolAddress(&p, g_h1); h1 = (float*)p;
    cudaGetSymbolAddress(&p, g_h2); h2 = (float*)p;
    cudaGetSymbolAddress(&p, g_h);  h  = (float*)p;
    cudaGetSymbolAddress(&p, g_vA); vA = (float*)p;
    cudaGetSymbolAddress(&p, g_vB); vB = (float*)p;

    __nv_bfloat16* h1hi = (__nv_bfloat16*)h1;
    __nv_bfloat16* h1lo = h1hi + (size_t)N_NODES * NHID;
    __nv_bfloat16* h2hi = (__nv_bfloat16*)h2;
    __nv_bfloat16* h2lo = h2hi + (size_t)N_NODES * NHID;

    // ---- CSR build ----
    zero_counts <<<(N_NODES + 255) / 256, 256>>>();
    count_deg   <<<(N_EDGES + 255) / 256, 256>>>(rows);
    compute_dinv<<<(N_NODES + 255) / 256, 256>>>();
    scan_blocks <<<NBLK, SCAN_T>>>();
    scan_offsets<<<1, 32>>>();
    scan_add    <<<NBLK, SCAN_T>>>();
    scatter_edges<<<(N_EDGES + 255) / 256, 256>>>(rows, cols);

    // ---- MLP via HMMA bf16 3-term split, pre-split intermediates ----
    const int SMEM_128 = 2 * (128 * RSB) + 2 * (128 * RSB) + 128 * 4;  // 74240
    const int SMEM_64  = 2 * (128 * RSB) + 2 * (64 * RSB) + 64 * 4;    // 55552
    cudaFuncSetAttribute((const void*)gemm_hmma<128, 1, 0, 1>,
                         cudaFuncAttributeMaxDynamicSharedMemorySize, SMEM_128);
    cudaFuncSetAttribute((const void*)gemm_hmma<128, 1, 1, 1>,
                         cudaFuncAttributeMaxDynamicSharedMemorySize, SMEM_128);
    cudaFuncSetAttribute((const void*)gemm_hmma<64, 0, 1, 0>,
                         cudaFuncAttributeMaxDynamicSharedMemorySize, SMEM_64);

    const int MG = (N_NODES + 127) / 128;   // 782
    gemm_hmma<128, 1, 0, 1><<<dim3(2, MG), 256, SMEM_128>>>(
        x, nullptr, nullptr, W1, b1, nullptr, h1hi, h1lo, N_NODES, NHID, NFEAT);
    gemm_hmma<128, 1, 1, 1><<<dim3(2, MG), 256, SMEM_128>>>(
        nullptr, h1hi, h1lo, W2, b2, nullptr, h2hi, h2lo, N_NODES, NHID, NHID);
    gemm_hmma<64, 0, 1, 0><<<dim3(1, MG), 256, SMEM_64>>>(
        nullptr, h2hi, h2lo, W3, b3, h, nullptr, nullptr, N_NODES, NCLASS, NHID);

    // ---- 10 power iterations ----
    const int SP_G = (N_NODES * NF4 + 319) / 320;
    const float* src = h;
    for (int it = 0; it < 10; it++) {
        float* dst = (it == 9) ? out : ((it & 1) ? vB : vA);
        spmm_step<<<SP_G, 320>>>((const float4*)src, (const float4*)h, (float4*)dst);
        src = dst;
    }
}